// round 14
// baseline (speedup 1.0000x reference)
#include <cuda_runtime.h>
#include <cuda.h>
#include <cuda_fp16.h>
#include <cstdint>

#define M_TOK 4096
#define N_OUT 4096
#define K_IN  4096

#if defined(__CUDA_ARCH_FEAT_SM103_ALL) \
    || (defined(__CUDA_ARCH_SPECIFIC__) && (__CUDA_ARCH_SPECIFIC__ == 1030)) \
    || (defined(__CUDA_ARCH_FAMILY_SPECIFIC__) && (__CUDA_ARCH_FAMILY_SPECIFIC__ == 1030))
#define HAS_TC 1
#else
#define HAS_TC 0
#endif

// Scratch (static __device__ per allocation-free rule): 2 x 32MB fp16
__device__ __half g_A[(size_t)M_TOK * K_IN];
__device__ __half g_W[(size_t)N_OUT * K_IN];
__device__ int g_has_tcgen05;          // set by gemm_tc
__device__ unsigned g_aband[16];       // A row-band ready counters (256 rows each)
__device__ unsigned g_wband[8];        // W row-band ready counters (512 rows each)

#define NPREP 448                      // prep CTAs; target count per band
#define PREP_THREADS (NPREP * 256)     // 114688

// ---------------------------------------------------------------------------
// Common PTX helpers
// ---------------------------------------------------------------------------
__device__ __forceinline__ uint32_t smem_to_u32(const void* p) {
    uint32_t a;
    asm("{ .reg .u64 t; cvta.to.shared.u64 t, %1; cvt.u32.u64 %0, t; }"
        : "=r"(a) : "l"(p));
    return a;
}
__device__ __forceinline__ void cp_async16(uint32_t dst, const void* src) {
    asm volatile("cp.async.cg.shared.global [%0], [%1], 16;\n" :: "r"(dst), "l"(src));
}
__device__ __forceinline__ void cp_commit() {
    asm volatile("cp.async.commit_group;\n");
}
template <int N> __device__ __forceinline__ void cp_wait() {
    asm volatile("cp.async.wait_group %0;\n" :: "n"(N));
}
__device__ __forceinline__ void ldsm4(uint32_t* r, uint32_t addr) {
    asm volatile("ldmatrix.sync.aligned.m8n8.x4.shared.b16 {%0,%1,%2,%3}, [%4];"
        : "=r"(r[0]), "=r"(r[1]), "=r"(r[2]), "=r"(r[3]) : "r"(addr));
}
__device__ __forceinline__ void mma16816h(float* c, const uint32_t* a, const uint32_t* b) {
    asm volatile(
        "mma.sync.aligned.m16n8k16.row.col.f32.f16.f16.f32 "
        "{%0,%1,%2,%3}, {%4,%5,%6,%7}, {%8,%9}, {%0,%1,%2,%3};\n"
        : "+f"(c[0]), "+f"(c[1]), "+f"(c[2]), "+f"(c[3])
        : "r"(a[0]), "r"(a[1]), "r"(a[2]), "r"(a[3]), "r"(b[0]), "r"(b[1]));
}

#define MBARRIER_INIT(mbar, count) \
    asm volatile("mbarrier.init.shared.b64 [%0], %1;" \
        :: "r"((uint32_t)(mbar)), "r"((uint32_t)(count)) : "memory")
#define MBARRIER_EXPECT_TX(mbar, tx) \
    asm volatile("mbarrier.arrive.expect_tx.shared.b64 _, [%0], %1;" \
        :: "r"((uint32_t)(mbar)), "r"((uint32_t)(tx)) : "memory")
#define MBARRIER_WAIT_PARITY(mbar, parity) do { \
    uint32_t _m = (uint32_t)(mbar), _p = (uint32_t)(parity), _d; \
    asm volatile("{\n\t.reg .pred p;\n\t" \
        "mbarrier.try_wait.parity.acquire.cta.shared::cta.b64 p, [%1], %2;\n\t" \
        "selp.b32 %0, 1, 0, p;\n\t}" : "=r"(_d) : "r"(_m), "r"(_p) : "memory"); \
    if (!_d) { \
        asm volatile("{\n\t.reg .pred P1;\n\t" \
            "WL_%=:\n\t" \
            "mbarrier.try_wait.parity.acquire.cta.shared::cta.b64 P1, [%0], %1, 0x989680;\n\t" \
            "@P1 bra.uni WD_%=;\n\t" \
            "bra.uni WL_%=;\n\t" \
            "WD_%=:\n\t}" :: "r"(_m), "r"(_p) : "memory"); \
    } \
} while (0)
#define FENCE_PROXY_ASYNC_SHARED_CTA() \
    asm volatile("fence.proxy.async.shared::cta;" ::: "memory")
#define CLUSTER_SYNC() do { \
    asm volatile("barrier.cluster.arrive.aligned;" ::: "memory"); \
    asm volatile("barrier.cluster.wait.aligned;" ::: "memory"); \
} while (0)

__device__ __forceinline__ void band_signal(unsigned* ctr) {
    __syncthreads();   // all CTA stores for this band done & visible
    if (threadIdx.x == 0)
        asm volatile("red.release.gpu.global.add.u32 [%0], 1;"
                     :: "l"(ctr) : "memory");
}
__device__ __forceinline__ void band_wait(const unsigned* ctr, unsigned target) {
    unsigned v;
    for (;;) {
        asm volatile("ld.acquire.gpu.global.u32 %0, [%1];" : "=r"(v) : "l"(ctr));
        if (v >= target) break;
        __nanosleep(256);
    }
}

// ---------------------------------------------------------------------------
__global__ void zero_counters() {
    if (threadIdx.x < 16) g_aband[threadIdx.x] = 0;
    if (threadIdx.x < 8)  g_wband[threadIdx.x] = 0;
}

// ---------------------------------------------------------------------------
// Banded prep (PDL primary): triggers dependent launch immediately, then
// produces A in 16 bands (256 rows) and W in 8 bands (512 rows).
// 448 CTAs x 256 threads (0 smem) -> GEMM CTAs always have room to co-reside.
// ---------------------------------------------------------------------------
__global__ __launch_bounds__(256) void prep_overlap(
    const float* __restrict__ x,
    const void* __restrict__ bases_raw,
    const float* __restrict__ alphas) {
    // Let the dependent (gemm_tc) launch now; it self-gates on band counters.
    asm volatile("griddepcontrol.launch_dependents;" ::: "memory");

    const int gt = blockIdx.x * 256 + threadIdx.x;   // 0 .. PREP_THREADS-1

    // ---- A bands: 16 x (262144 float4 units) ----
    #pragma unroll 1
    for (int b = 0; b < 16; b++) {
        for (int u = gt; u < 262144; u += PREP_THREADS) {
            const int idx = b * 262144 + u;          // float4 index
            float4 v = ((const float4*)x)[idx];
            union { __half2 h2[2]; uint2 uu; } hv;
            hv.h2[0] = __floats2half2_rn(v.x, v.y);
            hv.h2[1] = __floats2half2_rn(v.z, v.w);
            *(uint2*)(g_A + (size_t)idx * 4) = hv.uu;
        }
        band_signal(&g_aband[b]);
    }

    // ---- dtype detection (L2-hot 64B) ----
    const int* bw = (const int*)bases_raw;
    int is_i32 = 1;
    #pragma unroll
    for (int i = 0; i < 16; i++) {
        const int v = __ldg(bw + i);
        if (v != 1 && v != -1) is_i32 = 0;
    }
    const float a0 = __ldg(alphas + 0), a1 = __ldg(alphas + 1);
    const float a2 = __ldg(alphas + 2), a3 = __ldg(alphas + 3);

    // ---- W bands: 8 x (262144 8-elem units) ----
    #pragma unroll 1
    for (int b = 0; b < 8; b++) {
        for (int u = gt; u < 262144; u += PREP_THREADS) {
            const int idx = b * 262144 + u;          // 8-elem unit index
            float w[8];
            if (is_i32) {
                const size_t plane4 = (size_t)N_OUT * K_IN / 4;
                const int4* bp = (const int4*)bases_raw;
                int4 r[4][2];
                #pragma unroll
                for (int k = 0; k < 4; k++) {
                    r[k][0] = bp[k * plane4 + (size_t)idx * 2];
                    r[k][1] = bp[k * plane4 + (size_t)idx * 2 + 1];
                }
                #pragma unroll
                for (int h = 0; h < 2; h++) {
                    w[h * 4 + 0] = a0 * (float)r[0][h].x + a1 * (float)r[1][h].x
                                 + a2 * (float)r[2][h].x + a3 * (float)r[3][h].x;
                    w[h * 4 + 1] = a0 * (float)r[0][h].y + a1 * (float)r[1][h].y
                                 + a2 * (float)r[2][h].y + a3 * (float)r[3][h].y;
                    w[h * 4 + 2] = a0 * (float)r[0][h].z + a1 * (float)r[1][h].z
                                 + a2 * (float)r[2][h].z + a3 * (float)r[3][h].z;
                    w[h * 4 + 3] = a0 * (float)r[0][h].w + a1 * (float)r[1][h].w
                                 + a2 * (float)r[2][h].w + a3 * (float)r[3][h].w;
                }
            } else {
                const size_t plane8 = (size_t)N_OUT * K_IN / 8;
                const uint2* bp = (const uint2*)bases_raw;
                #pragma unroll
                for (int e = 0; e < 8; e++) w[e] = 0.f;
                #pragma unroll
                for (int k = 0; k < 4; k++) {
                    const float ak = (k == 0) ? a0 : (k == 1) ? a1 : (k == 2) ? a2 : a3;
                    union { uint2 uu; char c[8]; } r;
                    r.uu = bp[k * plane8 + idx];
                    #pragma unroll
                    for (int e = 0; e < 8; e++) w[e] += ak * (float)r.c[e];
                }
            }
            union { __half2 h2[4]; uint4 uu; } hv;
            hv.h2[0] = __floats2half2_rn(w[0], w[1]);
            hv.h2[1] = __floats2half2_rn(w[2], w[3]);
            hv.h2[2] = __floats2half2_rn(w[4], w[5]);
            hv.h2[3] = __floats2half2_rn(w[6], w[7]);
            *(uint4*)(g_W + (size_t)idx * 8) = hv.uu;
        }
        band_signal(&g_wband[b]);
    }
}

// ===========================================================================
// Path 1: HMMA fallback — gates on band counters (PDL decouples ordering).
// ===========================================================================
#define BKH 32
#define LDT 40
#define TILE_B (128 * LDT * 2)
#define STG_B  (2 * TILE_B)
#define HMMA_SMEM (2 * STG_B)

__global__ __launch_bounds__(256) void gemm_hmma(float* __restrict__ C) {
    if (g_has_tcgen05) return;

    extern __shared__ char smem[];
    const uint32_t sb = smem_to_u32(smem);
    const int tid = threadIdx.x;
    const int bm = blockIdx.y, bn = blockIdx.x;

    if (tid == 0) {
        band_wait(&g_aband[bm >> 1], NPREP);   // 256-row A bands
        band_wait(&g_wband[bn >> 2], NPREP);   // 512-row W bands
    }
    __syncthreads();

    const int lrow = tid >> 2;
    const int lch  = (tid & 3) * 8;
    const __half* gA0 = g_A + (size_t)(bm * 128 + lrow) * K_IN + lch;
    const __half* gB0 = g_W + (size_t)(bn * 128 + lrow) * K_IN + lch;
    const size_t half_rows = (size_t)64 * K_IN;
    const uint32_t dOff = (uint32_t)(lrow * LDT + lch) * 2;
    const uint32_t hOff = 64 * LDT * 2;

    const int warp = tid >> 5, lane = tid & 31;
    const int wm = warp & 1;
    const int wn = warp >> 1;
    const int g  = lane >> 2;
    const int tg = lane & 3;

    const uint32_t aoff =
        ((uint32_t)(wm * 64 + (lane & 7) + ((lane >> 3) & 1) * 8) * LDT
         + ((lane >> 4) & 1) * 8) * 2;
    const uint32_t boff =
        ((uint32_t)(wn * 32 + (lane & 7) + ((lane >> 4) & 1) * 8) * LDT
         + ((lane >> 3) & 1) * 8) * 2;

    float acc[4][4][4];
    #pragma unroll
    for (int mi = 0; mi < 4; mi++)
        #pragma unroll
        for (int ni = 0; ni < 4; ni++)
            #pragma unroll
            for (int e = 0; e < 4; e++) acc[mi][ni][e] = 0.f;

    const int NK = K_IN / BKH;

    {
        uint32_t d = sb + dOff;
        cp_async16(d, gA0);            cp_async16(d + hOff, gA0 + half_rows);
        cp_async16(d + TILE_B, gB0);   cp_async16(d + TILE_B + hOff, gB0 + half_rows);
        cp_commit();
    }

    for (int kt = 0; kt < NK; ++kt) {
        const int buf = kt & 1;
        if (kt + 1 < NK) {
            const int nb = (kt + 1) & 1;
            const size_t ko = (size_t)(kt + 1) * BKH;
            uint32_t d = sb + nb * STG_B + dOff;
            cp_async16(d, gA0 + ko);           cp_async16(d + hOff, gA0 + half_rows + ko);
            cp_async16(d + TILE_B, gB0 + ko);  cp_async16(d + TILE_B + hOff, gB0 + half_rows + ko);
            cp_commit();
            cp_wait<1>();
        } else {
            cp_wait<0>();
        }
        __syncthreads();

        const uint32_t base = sb + buf * STG_B;

        #pragma unroll
        for (int ks2 = 0; ks2 < 2; ks2++) {
            const uint32_t ko = ks2 * 32;
            uint32_t a[4][4], b[2][4];
            #pragma unroll
            for (int mi = 0; mi < 4; mi++)
                ldsm4(a[mi], base + aoff + mi * (16 * LDT * 2) + ko);
            #pragma unroll
            for (int nj = 0; nj < 2; nj++)
                ldsm4(b[nj], base + TILE_B + boff + nj * (16 * LDT * 2) + ko);

            #pragma unroll
            for (int mi = 0; mi < 4; mi++)
                #pragma unroll
                for (int ni = 0; ni < 4; ni++)
                    mma16816h(acc[mi][ni], a[mi], &b[ni >> 1][(ni & 1) * 2]);
        }
        __syncthreads();
    }

    #pragma unroll
    for (int mi = 0; mi < 4; mi++) {
        #pragma unroll
        for (int ni = 0; ni < 4; ni++) {
            const int row = bm * 128 + wm * 64 + mi * 16 + g;
            const int col = bn * 128 + wn * 32 + ni * 8 + tg * 2;
            *(float2*)(C + (size_t)row * N_OUT + col) =
                make_float2(acc[mi][ni][0], acc[mi][ni][1]);
            *(float2*)(C + (size_t)(row + 8) * N_OUT + col) =
                make_float2(acc[mi][ni][2], acc[mi][ni][3]);
        }
    }
}

// ===========================================================================
// Path 2: tcgen05 cg2 fp16 GEMM (proven round-11/12 structure) + band gate.
// Cluster tile 256(M) x 512(N), BK=64, 4 stages, deferred-wait schedule.
// ===========================================================================
#define BM 256
#define BN 512
#define BK 64
#define NCHUNK (K_IN / BK)   // 64
#define STAGES 4
#define A_BYTES (128 * BK * 2)
#define BSL_BYTES (128 * BK * 2)
#define STG_BYTES (A_BYTES + 2 * BSL_BYTES)   // 49152
#define CL_STG_BYTES (2 * STG_BYTES)          // 98304
#define SM_TMA_FULL(s) ((s) * 8)
#define SM_MMA_DONE(s) (64 + (s) * 8)
#define SM_TMEM_PTR    128
#define SM_TILES       1024
#define SM_A(s)  (SM_TILES + (s) * STG_BYTES)
#define SM_B1(s) (SM_A(s) + A_BYTES)
#define SM_B2(s) (SM_B1(s) + BSL_BYTES)
#define TC_SMEM (SM_TILES + STAGES * STG_BYTES)   // 197632
#define GEMM_IDESC ((1u << 4) | ((256u / 8) << 17) | ((256u / 16) << 24))

#if HAS_TC
static constexpr uint64_t SMEM_DESC_BASE_SW128 =
    (uint64_t(2) << 61) | (uint64_t(1) << 46) | (uint64_t(64) << 32) | (uint64_t(1) << 16);
#define MAKE_SMEM_DESC(addr) \
    (SMEM_DESC_BASE_SW128 | ((uint64_t)((addr) >> 4) & 0x3FFF))

__device__ __forceinline__ void mma_f16_ss_cg2(uint32_t d_tmem, uint64_t a_desc,
                                               uint64_t b_desc, uint32_t idesc,
                                               uint32_t enable) {
    asm volatile(
        "{\n\t.reg .pred p;\n\t"
        "setp.ne.u32 p, %5, 0;\n\t"
        "tcgen05.mma.cta_group::2.kind::f16 [%0], %1, %2, %3, "
        "{%4,%4,%4,%4,%4,%4,%4,%4}, p;\n\t}"
        :: "r"(d_tmem), "l"(a_desc), "l"(b_desc), "r"(idesc), "r"(0u), "r"(enable)
        : "memory");
}
__device__ __forceinline__ void tma_load_2d_cg2(uint32_t smem_addr,
                                                const CUtensorMap* tm,
                                                int x, int y, uint32_t mbar) {
    asm volatile(
        "{\n\t.reg .b32 lb;\n\t"
        "and.b32 lb, %4, 0xFEFFFFFF;\n\t"
        "cp.async.bulk.tensor.2d.cta_group::2.shared::cluster.global.tile"
        ".mbarrier::complete_tx::bytes [%0], [%1, {%2, %3}], [lb];\n\t}"
        :: "r"(smem_addr), "l"(tm), "r"(x), "r"(y), "r"(mbar) : "memory");
}
#define TCGEN05_COMMIT_MC_CG2(mbar, mask) \
    asm volatile("tcgen05.commit.cta_group::2.mbarrier::arrive::one.shared::cluster.multicast::cluster.b64 [%0], %1;" \
        :: "r"((uint32_t)(mbar)), "h"((uint16_t)(mask)) : "memory")
#endif  // HAS_TC

__global__ __launch_bounds__(256, 1) __cluster_dims__(2, 1, 1)
void gemm_tc(
    float* __restrict__ C,
    const __grid_constant__ CUtensorMap tm_a,
    const __grid_constant__ CUtensorMap tm_b) {
#if HAS_TC
    extern __shared__ char smem[];
    const uint32_t sb = smem_to_u32(smem);
    const int tid = threadIdx.x;
    const int wid = tid >> 5, lane = tid & 31;
    const int bm = blockIdx.x >> 1;            // 16 cluster-M tiles
    const int bn = blockIdx.y;                 // 8 cluster-N tiles
    uint32_t rank;
    asm("mov.u32 %0, %%cluster_ctarank;" : "=r"(rank));

    if (tid == 0 && blockIdx.x == 0 && blockIdx.y == 0) g_has_tcgen05 = 1;

    if (tid == 0) {
        #pragma unroll
        for (int s = 0; s < STAGES; s++) {
            MBARRIER_INIT(sb + SM_TMA_FULL(s), 1);
            MBARRIER_INIT(sb + SM_MMA_DONE(s), 1);
        }
        FENCE_PROXY_ASYNC_SHARED_CTA();
    }
    if (wid == 0) {
        asm volatile("tcgen05.alloc.cta_group::2.sync.aligned.shared::cta.b32 [%0], %1;"
            :: "r"(sb + SM_TMEM_PTR), "r"(512u) : "memory");
        asm volatile("tcgen05.relinquish_alloc_permit.cta_group::2.sync.aligned;");
    }
    __syncthreads();
    CLUSTER_SYNC();

    uint32_t tmem;
    asm volatile("ld.shared.b32 %0, [%1];" : "=r"(tmem) : "r"(sb + SM_TMEM_PTR));
    const uint32_t d1 = tmem;
    const uint32_t d2 = tmem + 256;

    const int a_row  = bm * BM + (int)rank * 128;
    const int b1_row = bn * BN + (int)rank * 128;
    const int b2_row = bn * BN + 256 + (int)rank * 128;

    if (tid == 0) {
        // Gate on the banded prep (may run concurrently under PDL; already
        // complete if the launch was serialized).
        band_wait(&g_aband[bm], NPREP);
        band_wait(&g_wband[bn], NPREP);
        asm volatile("fence.proxy.async;" ::: "memory");

        #pragma unroll
        for (int p = 0; p < STAGES; p++) {
            if (rank == 0) MBARRIER_EXPECT_TX(sb + SM_TMA_FULL(p), CL_STG_BYTES);
            const int kx = p * BK;
            tma_load_2d_cg2(sb + SM_A(p),  &tm_a, kx, a_row,  sb + SM_TMA_FULL(p));
            tma_load_2d_cg2(sb + SM_B1(p), &tm_b, kx, b1_row, sb + SM_TMA_FULL(p));
            tma_load_2d_cg2(sb + SM_B2(p), &tm_b, kx, b2_row, sb + SM_TMA_FULL(p));
        }

        for (int kt = 0; kt < NCHUNK; kt++) {
            const int s = kt & (STAGES - 1);
            const int ph = (kt / STAGES) & 1;

            if (rank == 0) {
                MBARRIER_WAIT_PARITY(sb + SM_TMA_FULL(s), ph);
                const uint64_t da  = MAKE_SMEM_DESC(sb + SM_A(s));
                const uint64_t db1 = MAKE_SMEM_DESC(sb + SM_B1(s));
                const uint64_t db2 = MAKE_SMEM_DESC(sb + SM_B2(s));
                #pragma unroll
                for (int ks = 0; ks < 4; ks++) {
                    const uint64_t o = (uint64_t)(ks * 2);
                    const uint32_t en = !(kt == 0 && ks == 0);
                    mma_f16_ss_cg2(d1, da + o, db1 + o, GEMM_IDESC, en);
                    mma_f16_ss_cg2(d2, da + o, db2 + o, GEMM_IDESC, en);
                }
                TCGEN05_COMMIT_MC_CG2(sb + SM_MMA_DONE(s), 3);
            }

            const int kp = kt - 1;
            if (kp >= 0 && kp + STAGES < NCHUNK) {
                const int sp = kp & (STAGES - 1);
                const int php = (kp / STAGES) & 1;
                MBARRIER_WAIT_PARITY(sb + SM_MMA_DONE(sp), php);
                if (rank == 0) MBARRIER_EXPECT_TX(sb + SM_TMA_FULL(sp), CL_STG_BYTES);
                const int kx = (kp + STAGES) * BK;
                tma_load_2d_cg2(sb + SM_A(sp),  &tm_a, kx, a_row,  sb + SM_TMA_FULL(sp));
                tma_load_2d_cg2(sb + SM_B1(sp), &tm_b, kx, b1_row, sb + SM_TMA_FULL(sp));
                tma_load_2d_cg2(sb + SM_B2(sp), &tm_b, kx, b2_row, sb + SM_TMA_FULL(sp));
            }
        }
        MBARRIER_WAIT_PARITY(sb + SM_MMA_DONE((NCHUNK - 1) & (STAGES - 1)),
                             ((NCHUNK - 1) / STAGES) & 1);
        asm volatile("tcgen05.fence::before_thread_sync;" ::: "memory");
    }
    __syncthreads();

    {
        asm volatile("tcgen05.fence::after_thread_sync;" ::: "memory");
        const uint32_t dbase = (wid < 4) ? d1 : d2;
        const int row = bm * BM + (int)rank * 128 + (wid & 3) * 32 + lane;
        const int col0 = bn * BN + ((wid < 4) ? 0 : 256);
        float* crow = C + (size_t)row * N_OUT + col0;
        #pragma unroll
        for (int base = 0; base < 256; base += 32) {
            uint32_t d[32];
            asm volatile("tcgen05.ld.sync.aligned.32x32b.x32.b32 "
                "{%0,%1,%2,%3,%4,%5,%6,%7,%8,%9,%10,%11,%12,%13,%14,%15,"
                "%16,%17,%18,%19,%20,%21,%22,%23,%24,%25,%26,%27,%28,%29,%30,%31}, [%32];"
                : "=r"(d[0]), "=r"(d[1]), "=r"(d[2]), "=r"(d[3]),
                  "=r"(d[4]), "=r"(d[5]), "=r"(d[6]), "=r"(d[7]),
                  "=r"(d[8]), "=r"(d[9]), "=r"(d[10]), "=r"(d[11]),
                  "=r"(d[12]), "=r"(d[13]), "=r"(d[14]), "=r"(d[15]),
                  "=r"(d[16]), "=r"(d[17]), "=r"(d[18]), "=r"(d[19]),
                  "=r"(d[20]), "=r"(d[21]), "=r"(d[22]), "=r"(d[23]),
                  "=r"(d[24]), "=r"(d[25]), "=r"(d[26]), "=r"(d[27]),
                  "=r"(d[28]), "=r"(d[29]), "=r"(d[30]), "=r"(d[31])
                : "r"(dbase + base));
            asm volatile("tcgen05.wait::ld.sync.aligned;" ::: "memory");
            #pragma unroll
            for (int j = 0; j < 8; j++) {
                float4 v;
                v.x = __uint_as_float(d[4 * j + 0]);
                v.y = __uint_as_float(d[4 * j + 1]);
                v.z = __uint_as_float(d[4 * j + 2]);
                v.w = __uint_as_float(d[4 * j + 3]);
                *(float4*)(crow + base + 4 * j) = v;
            }
        }
    }
    __syncthreads();
    if (wid == 0) {
        asm volatile("tcgen05.dealloc.cta_group::2.sync.aligned.b32 %0, %1;"
            :: "r"(tmem), "r"(512u));
    }
    CLUSTER_SYNC();
#endif  // HAS_TC
}

// ---------------------------------------------------------------------------
// Host
// ---------------------------------------------------------------------------
typedef CUresult (*encode_fn_t)(
    CUtensorMap*, CUtensorMapDataType, cuuint32_t, void*,
    const cuuint64_t*, const cuuint64_t*, const cuuint32_t*, const cuuint32_t*,
    CUtensorMapInterleave, CUtensorMapSwizzle, CUtensorMapL2promotion,
    CUtensorMapFloatOOBfill);

static void encode_map(encode_fn_t fn, CUtensorMap* tm, void* base,
                       int rows, uint32_t box_rows) {
    if (!fn) return;
    cuuint64_t dims[2] = {(cuuint64_t)K_IN, (cuuint64_t)rows};
    cuuint64_t strides[1] = {(cuuint64_t)K_IN * 2};
    cuuint32_t box[2] = {(cuuint32_t)BK, box_rows};
    cuuint32_t es[2] = {1, 1};
    fn(tm, CU_TENSOR_MAP_DATA_TYPE_FLOAT16, 2, base, dims, strides, box, es,
       CU_TENSOR_MAP_INTERLEAVE_NONE, CU_TENSOR_MAP_SWIZZLE_128B,
       CU_TENSOR_MAP_L2_PROMOTION_L2_128B, CU_TENSOR_MAP_FLOAT_OOB_FILL_NONE);
}

extern "C" void kernel_launch(void* const* d_in, const int* in_sizes, int n_in,
                              void* d_out, int out_size) {
    const float* x = nullptr;
    const float* alphas = nullptr;
    const void* bases = nullptr;
    for (int i = 0; i < n_in; i++) {
        if (in_sizes[i] == 4) alphas = (const float*)d_in[i];
        else if (in_sizes[i] == 16777216) x = (const float*)d_in[i];
        else if (in_sizes[i] == 67108864) bases = (const void*)d_in[i];
    }
    float* y = (float*)d_out;

    void* fnp = nullptr;
    cudaDriverEntryPointQueryResult qst;
#if CUDART_VERSION >= 12050
    cudaGetDriverEntryPointByVersion("cuTensorMapEncodeTiled", &fnp, 12000,
                                     cudaEnableDefault, &qst);
#else
    cudaGetDriverEntryPoint("cuTensorMapEncodeTiled", &fnp, cudaEnableDefault, &qst);
#endif
    encode_fn_t enc = (encode_fn_t)fnp;

    void *pA, *pW;
    cudaGetSymbolAddress(&pA, g_A);
    cudaGetSymbolAddress(&pW, g_W);

    CUtensorMap tm_a = {}, tm_b = {};
    encode_map(enc, &tm_a, pA, M_TOK, 128);
    encode_map(enc, &tm_b, pW, N_OUT, 128);

    cudaFuncSetAttribute(gemm_hmma,
                         cudaFuncAttributeMaxDynamicSharedMemorySize, HMMA_SMEM);
    cudaFuncSetAttribute(gemm_tc,
                         cudaFuncAttributeMaxDynamicSharedMemorySize, TC_SMEM);

    // 1) Reset band counters.
    zero_counters<<<1, 32>>>();

    // 2) Prep (PDL primary): triggers dependents at kernel start.
    prep_overlap<<<NPREP, 256>>>(x, bases, alphas);

    // 3) GEMM as PDL secondary: may begin while prep runs; self-gates on
    //    band counters. Falls back to a plain (serial) launch if PDL is
    //    unavailable — identical results, round-12 timing.
    dim3 grid_tc(2 * (M_TOK / BM), N_OUT / BN);   // 32 x 8 CTAs (16x8 clusters)
    {
        cudaLaunchConfig_t cfg = {};
        cfg.gridDim = grid_tc;
        cfg.blockDim = dim3(256, 1, 1);
        cfg.dynamicSmemBytes = TC_SMEM;
        cudaLaunchAttribute at[1];
        at[0].id = cudaLaunchAttributeProgrammaticStreamSerialization;
        at[0].val.programmaticStreamSerializationAllowed = 1;
        cfg.attrs = at;
        cfg.numAttrs = 1;
        cudaError_t e = cudaLaunchKernelEx(&cfg, gemm_tc, y, tm_a, tm_b);
        if (e != cudaSuccess) {
            (void)cudaGetLastError();   // clear sticky error
            gemm_tc<<<grid_tc, 256, TC_SMEM>>>(y, tm_a, tm_b);
        }
    }

    // 4) Fallback GEMM (band-gated internally; no-op when tcgen05 ran).
    dim3 grid_h(N_OUT / 128, M_TOK / 128);
    gemm_hmma<<<grid_h, 256, HMMA_SMEM>>>(y);
}

// round 15
// speedup vs baseline: 1.1110x; 1.1110x over previous
#include <cuda_runtime.h>
#include <cuda.h>
#include <cuda_fp16.h>
#include <cstdint>

// ---------------------------------------------------------------------------
// Problem: y[4096,4096] = x[4096,4096] @ W^T, W = sum_k alpha_k * bases_k
// Single fp16 GEMM (fp32 accum). Measured norm rel-err: 3.9e-4 < 1e-3.
// ---------------------------------------------------------------------------
#define M_TOK 4096
#define N_OUT 4096
#define K_IN  4096

// Arch-specific (sm_103a) feature detection at compile time, per pass.
#if defined(__CUDA_ARCH_FEAT_SM103_ALL) \
    || (defined(__CUDA_ARCH_SPECIFIC__) && (__CUDA_ARCH_SPECIFIC__ == 1030)) \
    || (defined(__CUDA_ARCH_FAMILY_SPECIFIC__) && (__CUDA_ARCH_FAMILY_SPECIFIC__ == 1030))
#define HAS_TC 1
#else
#define HAS_TC 0
#endif

// Scratch (static __device__ per allocation-free rule): 2 x 32MB fp16
__device__ __half g_A[(size_t)M_TOK * K_IN];
__device__ __half g_W[(size_t)N_OUT * K_IN];
__device__ int g_has_tcgen05;   // set by gemm_tc (runs before gemm_hmma)

// ---------------------------------------------------------------------------
// Common PTX helpers
// ---------------------------------------------------------------------------
__device__ __forceinline__ uint32_t smem_to_u32(const void* p) {
    uint32_t a;
    asm("{ .reg .u64 t; cvta.to.shared.u64 t, %1; cvt.u32.u64 %0, t; }"
        : "=r"(a) : "l"(p));
    return a;
}
__device__ __forceinline__ void cp_async16(uint32_t dst, const void* src) {
    asm volatile("cp.async.cg.shared.global [%0], [%1], 16;\n" :: "r"(dst), "l"(src));
}
__device__ __forceinline__ void cp_commit() {
    asm volatile("cp.async.commit_group;\n");
}
template <int N> __device__ __forceinline__ void cp_wait() {
    asm volatile("cp.async.wait_group %0;\n" :: "n"(N));
}
__device__ __forceinline__ void ldsm4(uint32_t* r, uint32_t addr) {
    asm volatile("ldmatrix.sync.aligned.m8n8.x4.shared.b16 {%0,%1,%2,%3}, [%4];"
        : "=r"(r[0]), "=r"(r[1]), "=r"(r[2]), "=r"(r[3]) : "r"(addr));
}
__device__ __forceinline__ void mma16816h(float* c, const uint32_t* a, const uint32_t* b) {
    asm volatile(
        "mma.sync.aligned.m16n8k16.row.col.f32.f16.f16.f32 "
        "{%0,%1,%2,%3}, {%4,%5,%6,%7}, {%8,%9}, {%0,%1,%2,%3};\n"
        : "+f"(c[0]), "+f"(c[1]), "+f"(c[2]), "+f"(c[3])
        : "r"(a[0]), "r"(a[1]), "r"(a[2]), "r"(a[3]), "r"(b[0]), "r"(b[1]));
}

#define MBARRIER_INIT(mbar, count) \
    asm volatile("mbarrier.init.shared.b64 [%0], %1;" \
        :: "r"((uint32_t)(mbar)), "r"((uint32_t)(count)) : "memory")
#define MBARRIER_EXPECT_TX(mbar, tx) \
    asm volatile("mbarrier.arrive.expect_tx.shared.b64 _, [%0], %1;" \
        :: "r"((uint32_t)(mbar)), "r"((uint32_t)(tx)) : "memory")
#define MBARRIER_WAIT_PARITY(mbar, parity) do { \
    uint32_t _m = (uint32_t)(mbar), _p = (uint32_t)(parity), _d; \
    asm volatile("{\n\t.reg .pred p;\n\t" \
        "mbarrier.try_wait.parity.acquire.cta.shared::cta.b64 p, [%1], %2;\n\t" \
        "selp.b32 %0, 1, 0, p;\n\t}" : "=r"(_d) : "r"(_m), "r"(_p) : "memory"); \
    if (!_d) { \
        asm volatile("{\n\t.reg .pred P1;\n\t" \
            "WL_%=:\n\t" \
            "mbarrier.try_wait.parity.acquire.cta.shared::cta.b64 P1, [%0], %1, 0x989680;\n\t" \
            "@P1 bra.uni WD_%=;\n\t" \
            "bra.uni WL_%=;\n\t" \
            "WD_%=:\n\t}" :: "r"(_m), "r"(_p) : "memory"); \
    } \
} while (0)
#define FENCE_PROXY_ASYNC_SHARED_CTA() \
    asm volatile("fence.proxy.async.shared::cta;" ::: "memory")
#define CLUSTER_SYNC() do { \
    asm volatile("barrier.cluster.arrive.aligned;" ::: "memory"); \
    asm volatile("barrier.cluster.wait.aligned;" ::: "memory"); \
} while (0)

// ===========================================================================
// Fused prep: one kernel does x->fp16 (g_A) AND W=sum(alpha*base)->fp16 (g_W).
// Block-range split; dtype of `bases` detected per-block (L2-hot 64B read).
// `bases` is single-use: streamed with __ldcs so its 256 MB doesn't evict the
// freshly written g_A/g_W lines from L2 before the GEMM's first wave.
// ===========================================================================
#define PX_BLOCKS 16384   // (4096*4096/4) float4 items / 256 threads
#define PW_BLOCKS 8192    // (4096*4096/8) 8-elem items / 256 threads

__global__ __launch_bounds__(256) void prep_fused(
    const float* __restrict__ x,
    const void* __restrict__ bases_raw,
    const float* __restrict__ alphas) {
    const int tid = threadIdx.x;

    if (blockIdx.x < PX_BLOCKS) {
        // ---- X part: 4 fp32 -> 4 fp16 per thread ----
        const int idx = blockIdx.x * 256 + tid;
        float4 v = ((const float4*)x)[idx];
        union { __half2 h2[2]; uint2 u; } hv;
        hv.h2[0] = __floats2half2_rn(v.x, v.y);
        hv.h2[1] = __floats2half2_rn(v.z, v.w);
        *(uint2*)(g_A + (size_t)idx * 4) = hv.u;
    } else {
        // ---- W part: 8 elements per thread ----
        const int idx = (blockIdx.x - PX_BLOCKS) * 256 + tid;

        // Per-block dtype detection: if bases is int32, the first 16 words
        // are exactly +/-1; if packed int8, they decode to other patterns.
        const int* bw = (const int*)bases_raw;
        int is_i32 = 1;
        #pragma unroll
        for (int i = 0; i < 16; i++) {
            const int v = __ldg(bw + i);
            if (v != 1 && v != -1) is_i32 = 0;
        }

        const float a0 = __ldg(alphas + 0), a1 = __ldg(alphas + 1);
        const float a2 = __ldg(alphas + 2), a3 = __ldg(alphas + 3);

        float w[8];
        if (is_i32) {
            const size_t plane4 = (size_t)N_OUT * K_IN / 4;  // int4 units
            const int4* b = (const int4*)bases_raw;
            int4 r[4][2];
            #pragma unroll
            for (int k = 0; k < 4; k++) {
                r[k][0] = __ldcs(&b[k * plane4 + (size_t)idx * 2]);
                r[k][1] = __ldcs(&b[k * plane4 + (size_t)idx * 2 + 1]);
            }
            #pragma unroll
            for (int h = 0; h < 2; h++) {
                w[h * 4 + 0] = a0 * (float)r[0][h].x + a1 * (float)r[1][h].x
                             + a2 * (float)r[2][h].x + a3 * (float)r[3][h].x;
                w[h * 4 + 1] = a0 * (float)r[0][h].y + a1 * (float)r[1][h].y
                             + a2 * (float)r[2][h].y + a3 * (float)r[3][h].y;
                w[h * 4 + 2] = a0 * (float)r[0][h].z + a1 * (float)r[1][h].z
                             + a2 * (float)r[2][h].z + a3 * (float)r[3][h].z;
                w[h * 4 + 3] = a0 * (float)r[0][h].w + a1 * (float)r[1][h].w
                             + a2 * (float)r[2][h].w + a3 * (float)r[3][h].w;
            }
        } else {
            const size_t plane8 = (size_t)N_OUT * K_IN / 8;  // 8-byte units
            const uint2* b = (const uint2*)bases_raw;        // 8 int8 per load
            #pragma unroll
            for (int e = 0; e < 8; e++) w[e] = 0.f;
            #pragma unroll
            for (int k = 0; k < 4; k++) {
                const float ak = (k == 0) ? a0 : (k == 1) ? a1 : (k == 2) ? a2 : a3;
                union { uint2 u; char c[8]; } r;
                r.u = __ldcs(&b[k * plane8 + idx]);
                #pragma unroll
                for (int e = 0; e < 8; e++) w[e] += ak * (float)r.c[e];
            }
        }

        union { __half2 h2[4]; uint4 u; } hv;
        hv.h2[0] = __floats2half2_rn(w[0], w[1]);
        hv.h2[1] = __floats2half2_rn(w[2], w[3]);
        hv.h2[2] = __floats2half2_rn(w[4], w[5]);
        hv.h2[3] = __floats2half2_rn(w[6], w[7]);
        *(uint4*)(g_W + (size_t)idx * 8) = hv.u;
    }
}

// ===========================================================================
// Path 1: HMMA (mma.sync) GEMM — fallback if no tcgen05 pass loaded.
// ===========================================================================
#define BKH 32
#define LDT 40
#define TILE_B (128 * LDT * 2)
#define STG_B  (2 * TILE_B)
#define HMMA_SMEM (2 * STG_B)

__global__ __launch_bounds__(256) void gemm_hmma(float* __restrict__ C) {
    if (g_has_tcgen05) return;   // set by gemm_tc, which ran just before

    extern __shared__ char smem[];
    const uint32_t sb = smem_to_u32(smem);
    const int tid = threadIdx.x;
    const int bm = blockIdx.y, bn = blockIdx.x;

    const int lrow = tid >> 2;
    const int lch  = (tid & 3) * 8;
    const __half* gA0 = g_A + (size_t)(bm * 128 + lrow) * K_IN + lch;
    const __half* gB0 = g_W + (size_t)(bn * 128 + lrow) * K_IN + lch;
    const size_t half_rows = (size_t)64 * K_IN;
    const uint32_t dOff = (uint32_t)(lrow * LDT + lch) * 2;
    const uint32_t hOff = 64 * LDT * 2;

    const int warp = tid >> 5, lane = tid & 31;
    const int wm = warp & 1;
    const int wn = warp >> 1;
    const int g  = lane >> 2;
    const int tg = lane & 3;

    const uint32_t aoff =
        ((uint32_t)(wm * 64 + (lane & 7) + ((lane >> 3) & 1) * 8) * LDT
         + ((lane >> 4) & 1) * 8) * 2;
    const uint32_t boff =
        ((uint32_t)(wn * 32 + (lane & 7) + ((lane >> 4) & 1) * 8) * LDT
         + ((lane >> 3) & 1) * 8) * 2;

    float acc[4][4][4];
    #pragma unroll
    for (int mi = 0; mi < 4; mi++)
        #pragma unroll
        for (int ni = 0; ni < 4; ni++)
            #pragma unroll
            for (int e = 0; e < 4; e++) acc[mi][ni][e] = 0.f;

    const int NK = K_IN / BKH;

    {
        uint32_t d = sb + dOff;
        cp_async16(d, gA0);            cp_async16(d + hOff, gA0 + half_rows);
        cp_async16(d + TILE_B, gB0);   cp_async16(d + TILE_B + hOff, gB0 + half_rows);
        cp_commit();
    }

    for (int kt = 0; kt < NK; ++kt) {
        const int buf = kt & 1;
        if (kt + 1 < NK) {
            const int nb = (kt + 1) & 1;
            const size_t ko = (size_t)(kt + 1) * BKH;
            uint32_t d = sb + nb * STG_B + dOff;
            cp_async16(d, gA0 + ko);           cp_async16(d + hOff, gA0 + half_rows + ko);
            cp_async16(d + TILE_B, gB0 + ko);  cp_async16(d + TILE_B + hOff, gB0 + half_rows + ko);
            cp_commit();
            cp_wait<1>();
        } else {
            cp_wait<0>();
        }
        __syncthreads();

        const uint32_t base = sb + buf * STG_B;

        #pragma unroll
        for (int ks2 = 0; ks2 < 2; ks2++) {
            const uint32_t ko = ks2 * 32;
            uint32_t a[4][4], b[2][4];
            #pragma unroll
            for (int mi = 0; mi < 4; mi++)
                ldsm4(a[mi], base + aoff + mi * (16 * LDT * 2) + ko);
            #pragma unroll
            for (int nj = 0; nj < 2; nj++)
                ldsm4(b[nj], base + TILE_B + boff + nj * (16 * LDT * 2) + ko);

            #pragma unroll
            for (int mi = 0; mi < 4; mi++)
                #pragma unroll
                for (int ni = 0; ni < 4; ni++)
                    mma16816h(acc[mi][ni], a[mi], &b[ni >> 1][(ni & 1) * 2]);
        }
        __syncthreads();
    }

    #pragma unroll
    for (int mi = 0; mi < 4; mi++) {
        #pragma unroll
        for (int ni = 0; ni < 4; ni++) {
            const int row = bm * 128 + wm * 64 + mi * 16 + g;
            const int col = bn * 128 + wn * 32 + ni * 8 + tg * 2;
            *(float2*)(C + (size_t)row * N_OUT + col) =
                make_float2(acc[mi][ni][0], acc[mi][ni][1]);
            *(float2*)(C + (size_t)(row + 8) * N_OUT + col) =
                make_float2(acc[mi][ni][2], acc[mi][ni][3]);
        }
    }
}

// ===========================================================================
// Path 2: tcgen05 cg2 fp16 GEMM — proven cluster tile 256x512, BK=64,
// 4 stages, deferred-wait schedule (round 11/12, 175.1us). Sets
// g_has_tcgen05 (replaces the probe kernel).
// ===========================================================================
#define BM 256            // cluster M
#define BN 512            // cluster N
#define BK 64
#define NCHUNK (K_IN / BK)   // 64
#define STAGES 4
#define A_BYTES (128 * BK * 2)          // 16384 per CTA (its M-half)
#define BSL_BYTES (128 * BK * 2)        // 16384 per B slice
#define STG_BYTES (A_BYTES + 2 * BSL_BYTES)   // 49152 per CTA
#define CL_STG_BYTES (2 * STG_BYTES)          // 98304 per cluster (expect_tx)
#define SM_TMA_FULL(s) ((s) * 8)
#define SM_MMA_DONE(s) (64 + (s) * 8)
#define SM_TMEM_PTR    128
#define SM_TILES       1024
#define SM_A(s)  (SM_TILES + (s) * STG_BYTES)
#define SM_B1(s) (SM_A(s) + A_BYTES)
#define SM_B2(s) (SM_B1(s) + BSL_BYTES)
#define TC_SMEM (SM_TILES + STAGES * STG_BYTES)   // 197632
// idesc kind::f16 cg2: dtype=F32(1<<4), f16 in (atype=btype=0), N=256, M=256
#define GEMM_IDESC ((1u << 4) | ((256u / 8) << 17) | ((256u / 16) << 24))

#if HAS_TC
static constexpr uint64_t SMEM_DESC_BASE_SW128 =
    (uint64_t(2) << 61) | (uint64_t(1) << 46) | (uint64_t(64) << 32) | (uint64_t(1) << 16);
#define MAKE_SMEM_DESC(addr) \
    (SMEM_DESC_BASE_SW128 | ((uint64_t)((addr) >> 4) & 0x3FFF))

__device__ __forceinline__ void mma_f16_ss_cg2(uint32_t d_tmem, uint64_t a_desc,
                                               uint64_t b_desc, uint32_t idesc,
                                               uint32_t enable) {
    asm volatile(
        "{\n\t.reg .pred p;\n\t"
        "setp.ne.u32 p, %5, 0;\n\t"
        "tcgen05.mma.cta_group::2.kind::f16 [%0], %1, %2, %3, "
        "{%4,%4,%4,%4,%4,%4,%4,%4}, p;\n\t}"
        :: "r"(d_tmem), "l"(a_desc), "l"(b_desc), "r"(idesc), "r"(0u), "r"(enable)
        : "memory");
}
// cg2 TMA: both CTAs execute; complete_tx targets the LEADER's barrier
// (clear bit 24 of the local barrier address).
__device__ __forceinline__ void tma_load_2d_cg2(uint32_t smem_addr,
                                                const CUtensorMap* tm,
                                                int x, int y, uint32_t mbar) {
    asm volatile(
        "{\n\t.reg .b32 lb;\n\t"
        "and.b32 lb, %4, 0xFEFFFFFF;\n\t"
        "cp.async.bulk.tensor.2d.cta_group::2.shared::cluster.global.tile"
        ".mbarrier::complete_tx::bytes [%0], [%1, {%2, %3}], [lb];\n\t}"
        :: "r"(smem_addr), "l"(tm), "r"(x), "r"(y), "r"(mbar) : "memory");
}
#define TCGEN05_COMMIT_MC_CG2(mbar, mask) \
    asm volatile("tcgen05.commit.cta_group::2.mbarrier::arrive::one.shared::cluster.multicast::cluster.b64 [%0], %1;" \
        :: "r"((uint32_t)(mbar)), "h"((uint16_t)(mask)) : "memory")
#endif  // HAS_TC

__global__ __launch_bounds__(256, 1) __cluster_dims__(2, 1, 1)
void gemm_tc(
    float* __restrict__ C,
    const __grid_constant__ CUtensorMap tm_a,
    const __grid_constant__ CUtensorMap tm_b) {
#if HAS_TC
    extern __shared__ char smem[];
    const uint32_t sb = smem_to_u32(smem);
    const int tid = threadIdx.x;
    const int wid = tid >> 5, lane = tid & 31;
    const int bm = blockIdx.x >> 1;            // 16 cluster-M tiles
    const int bn = blockIdx.y;                 // 8 cluster-N tiles
    uint32_t rank;
    asm("mov.u32 %0, %%cluster_ctarank;" : "=r"(rank));

    // Replaces the probe kernel: this pass has tcgen05, tell gemm_hmma.
    if (tid == 0 && blockIdx.x == 0 && blockIdx.y == 0) g_has_tcgen05 = 1;

    if (tid == 0) {
        #pragma unroll
        for (int s = 0; s < STAGES; s++) {
            MBARRIER_INIT(sb + SM_TMA_FULL(s), 1);   // leader-only use
            MBARRIER_INIT(sb + SM_MMA_DONE(s), 1);   // one mc-commit arrives
        }
        FENCE_PROXY_ASYNC_SHARED_CTA();
    }
    if (wid == 0) {
        asm volatile("tcgen05.alloc.cta_group::2.sync.aligned.shared::cta.b32 [%0], %1;"
            :: "r"(sb + SM_TMEM_PTR), "r"(512u) : "memory");
        asm volatile("tcgen05.relinquish_alloc_permit.cta_group::2.sync.aligned;");
    }
    __syncthreads();
    CLUSTER_SYNC();   // barriers + TMEM alloc visible before cg2 TMA/MMA

    uint32_t tmem;
    asm volatile("ld.shared.b32 %0, [%1];" : "=r"(tmem) : "r"(sb + SM_TMEM_PTR));
    const uint32_t d1 = tmem;         // N-cols [0,256)  (this CTA's 128 M-rows)
    const uint32_t d2 = tmem + 256;   // N-cols [256,512)

    // Per-CTA TMA coordinates
    const int a_row  = bm * BM + (int)rank * 128;          // A M-half
    const int b1_row = bn * BN + (int)rank * 128;          // B slice, MMA1
    const int b2_row = bn * BN + 256 + (int)rank * 128;    // B slice, MMA2

    if (tid == 0) {
        // Prologue: fill all stages (chunks 0..3)
        #pragma unroll
        for (int p = 0; p < STAGES; p++) {
            if (rank == 0) MBARRIER_EXPECT_TX(sb + SM_TMA_FULL(p), CL_STG_BYTES);
            const int kx = p * BK;
            tma_load_2d_cg2(sb + SM_A(p),  &tm_a, kx, a_row,  sb + SM_TMA_FULL(p));
            tma_load_2d_cg2(sb + SM_B1(p), &tm_b, kx, b1_row, sb + SM_TMA_FULL(p));
            tma_load_2d_cg2(sb + SM_B2(p), &tm_b, kx, b2_row, sb + SM_TMA_FULL(p));
        }

        for (int kt = 0; kt < NCHUNK; kt++) {
            const int s = kt & (STAGES - 1);
            const int ph = (kt / STAGES) & 1;

            if (rank == 0) {
                // Wait both CTAs' stage data (6 loads -> leader barrier).
                MBARRIER_WAIT_PARITY(sb + SM_TMA_FULL(s), ph);
                const uint64_t da  = MAKE_SMEM_DESC(sb + SM_A(s));
                const uint64_t db1 = MAKE_SMEM_DESC(sb + SM_B1(s));
                const uint64_t db2 = MAKE_SMEM_DESC(sb + SM_B2(s));
                #pragma unroll
                for (int ks = 0; ks < 4; ks++) {   // 4 x K16 per BK=64
                    const uint64_t o = (uint64_t)(ks * 2);
                    const uint32_t en = !(kt == 0 && ks == 0);
                    mma_f16_ss_cg2(d1, da + o, db1 + o, GEMM_IDESC, en);
                    mma_f16_ss_cg2(d2, da + o, db2 + o, GEMM_IDESC, en);
                }
                // Arrive on BOTH CTAs' MMA_DONE(s) when this batch completes.
                TCGEN05_COMMIT_MC_CG2(sb + SM_MMA_DONE(s), 3);
            }

            // Deferred refill: stage of chunk kp = kt-1, reloaded with chunk
            // kp+STAGES, gated on chunk kp's MMA completion (local mc-commit
            // arrival). Chunk kt's MMAs are queued behind kp's: tensor pipe
            // stays fed while blocking here.
            const int kp = kt - 1;
            if (kp >= 0 && kp + STAGES < NCHUNK) {
                const int sp = kp & (STAGES - 1);
                const int php = (kp / STAGES) & 1;
                MBARRIER_WAIT_PARITY(sb + SM_MMA_DONE(sp), php);
                if (rank == 0) MBARRIER_EXPECT_TX(sb + SM_TMA_FULL(sp), CL_STG_BYTES);
                const int kx = (kp + STAGES) * BK;
                tma_load_2d_cg2(sb + SM_A(sp),  &tm_a, kx, a_row,  sb + SM_TMA_FULL(sp));
                tma_load_2d_cg2(sb + SM_B1(sp), &tm_b, kx, b1_row, sb + SM_TMA_FULL(sp));
                tma_load_2d_cg2(sb + SM_B2(sp), &tm_b, kx, b2_row, sb + SM_TMA_FULL(sp));
            }
        }
        // Final: wait for the LAST chunk's mc-commit on the local barrier.
        MBARRIER_WAIT_PARITY(sb + SM_MMA_DONE((NCHUNK - 1) & (STAGES - 1)),
                             ((NCHUNK - 1) / STAGES) & 1);
        asm volatile("tcgen05.fence::before_thread_sync;" ::: "memory");
    }
    __syncthreads();

    // Epilogue: each CTA drains its own TMEM (its 128 M-rows x 512 N-cols).
    // Warps 0-3 -> D1 (N-cols 0-255), warps 4-7 -> D2 (N-cols 256-511).
    {
        asm volatile("tcgen05.fence::after_thread_sync;" ::: "memory");
        const uint32_t dbase = (wid < 4) ? d1 : d2;
        const int row = bm * BM + (int)rank * 128 + (wid & 3) * 32 + lane;
        const int col0 = bn * BN + ((wid < 4) ? 0 : 256);
        float* crow = C + (size_t)row * N_OUT + col0;
        #pragma unroll
        for (int base = 0; base < 256; base += 32) {
            uint32_t d[32];
            asm volatile("tcgen05.ld.sync.aligned.32x32b.x32.b32 "
                "{%0,%1,%2,%3,%4,%5,%6,%7,%8,%9,%10,%11,%12,%13,%14,%15,"
                "%16,%17,%18,%19,%20,%21,%22,%23,%24,%25,%26,%27,%28,%29,%30,%31}, [%32];"
                : "=r"(d[0]), "=r"(d[1]), "=r"(d[2]), "=r"(d[3]),
                  "=r"(d[4]), "=r"(d[5]), "=r"(d[6]), "=r"(d[7]),
                  "=r"(d[8]), "=r"(d[9]), "=r"(d[10]), "=r"(d[11]),
                  "=r"(d[12]), "=r"(d[13]), "=r"(d[14]), "=r"(d[15]),
                  "=r"(d[16]), "=r"(d[17]), "=r"(d[18]), "=r"(d[19]),
                  "=r"(d[20]), "=r"(d[21]), "=r"(d[22]), "=r"(d[23]),
                  "=r"(d[24]), "=r"(d[25]), "=r"(d[26]), "=r"(d[27]),
                  "=r"(d[28]), "=r"(d[29]), "=r"(d[30]), "=r"(d[31])
                : "r"(dbase + base));
            asm volatile("tcgen05.wait::ld.sync.aligned;" ::: "memory");
            #pragma unroll
            for (int j = 0; j < 8; j++) {
                float4 v;
                v.x = __uint_as_float(d[4 * j + 0]);
                v.y = __uint_as_float(d[4 * j + 1]);
                v.z = __uint_as_float(d[4 * j + 2]);
                v.w = __uint_as_float(d[4 * j + 3]);
                *(float4*)(crow + base + 4 * j) = v;
            }
        }
    }
    __syncthreads();
    if (wid == 0) {
        asm volatile("tcgen05.dealloc.cta_group::2.sync.aligned.b32 %0, %1;"
            :: "r"(tmem), "r"(512u));
    }
    // Peer MMA may read this CTA's SMEM until the end; TMEM is pair-shared.
    CLUSTER_SYNC();
#endif  // HAS_TC
}

// ---------------------------------------------------------------------------
// Host
// ---------------------------------------------------------------------------
typedef CUresult (*encode_fn_t)(
    CUtensorMap*, CUtensorMapDataType, cuuint32_t, void*,
    const cuuint64_t*, const cuuint64_t*, const cuuint32_t*, const cuuint32_t*,
    CUtensorMapInterleave, CUtensorMapSwizzle, CUtensorMapL2promotion,
    CUtensorMapFloatOOBfill);

static void encode_map(encode_fn_t fn, CUtensorMap* tm, void* base,
                       int rows, uint32_t box_rows) {
    if (!fn) return;
    cuuint64_t dims[2] = {(cuuint64_t)K_IN, (cuuint64_t)rows};
    cuuint64_t strides[1] = {(cuuint64_t)K_IN * 2};
    cuuint32_t box[2] = {(cuuint32_t)BK, box_rows};   // 64 fp16 = 128B = SW128 atom
    cuuint32_t es[2] = {1, 1};
    fn(tm, CU_TENSOR_MAP_DATA_TYPE_FLOAT16, 2, base, dims, strides, box, es,
       CU_TENSOR_MAP_INTERLEAVE_NONE, CU_TENSOR_MAP_SWIZZLE_128B,
       CU_TENSOR_MAP_L2_PROMOTION_L2_128B, CU_TENSOR_MAP_FLOAT_OOB_FILL_NONE);
}

extern "C" void kernel_launch(void* const* d_in, const int* in_sizes, int n_in,
                              void* d_out, int out_size) {
    const float* x = nullptr;
    const float* alphas = nullptr;
    const void* bases = nullptr;
    for (int i = 0; i < n_in; i++) {
        if (in_sizes[i] == 4) alphas = (const float*)d_in[i];
        else if (in_sizes[i] == 16777216) x = (const float*)d_in[i];
        else if (in_sizes[i] == 67108864) bases = (const void*)d_in[i];
    }
    float* y = (float*)d_out;

    void* fnp = nullptr;
    cudaDriverEntryPointQueryResult qst;
#if CUDART_VERSION >= 12050
    cudaGetDriverEntryPointByVersion("cuTensorMapEncodeTiled", &fnp, 12000,
                                     cudaEnableDefault, &qst);
#else
    cudaGetDriverEntryPoint("cuTensorMapEncodeTiled", &fnp, cudaEnableDefault, &qst);
#endif
    encode_fn_t enc = (encode_fn_t)fnp;

    void *pA, *pW;
    cudaGetSymbolAddress(&pA, g_A);
    cudaGetSymbolAddress(&pW, g_W);

    CUtensorMap tm_a = {}, tm_b = {};
    encode_map(enc, &tm_a, pA, M_TOK, 128);    // A box: 64 x 128 (M-half)
    encode_map(enc, &tm_b, pW, N_OUT, 128);    // B box: 64 x 128 (N-slice)

    cudaFuncSetAttribute(gemm_hmma,
                         cudaFuncAttributeMaxDynamicSharedMemorySize, HMMA_SMEM);
    cudaFuncSetAttribute(gemm_tc,
                         cudaFuncAttributeMaxDynamicSharedMemorySize, TC_SMEM);

    // One fused prep launch (x convert + W materialize + inline detection)
    prep_fused<<<PX_BLOCKS + PW_BLOCKS, 256>>>(x, bases, alphas);

    dim3 grid_tc(2 * (M_TOK / BM), N_OUT / BN);   // 32 x 8 CTAs (16x8 clusters)
    gemm_tc<<<grid_tc, 256, TC_SMEM>>>(y, tm_a, tm_b);

    dim3 grid_h(N_OUT / 128, M_TOK / 128);
    gemm_hmma<<<grid_h, 256, HMMA_SMEM>>>(y);
}

// round 16
// speedup vs baseline: 1.1369x; 1.0233x over previous
#include <cuda_runtime.h>
#include <cuda.h>
#include <cuda_fp16.h>
#include <cstdint>

// ---------------------------------------------------------------------------
// Problem: y[4096,4096] = x[4096,4096] @ W^T, W = sum_k alpha_k * bases_k
// Single fp16 GEMM (fp32 accum). Measured norm rel-err: 3.9e-4 < 1e-3.
// ---------------------------------------------------------------------------
#define M_TOK 4096
#define N_OUT 4096
#define K_IN  4096

// Arch-specific (sm_103a) feature detection at compile time, per pass.
#if defined(__CUDA_ARCH_FEAT_SM103_ALL) \
    || (defined(__CUDA_ARCH_SPECIFIC__) && (__CUDA_ARCH_SPECIFIC__ == 1030)) \
    || (defined(__CUDA_ARCH_FAMILY_SPECIFIC__) && (__CUDA_ARCH_FAMILY_SPECIFIC__ == 1030))
#define HAS_TC 1
#else
#define HAS_TC 0
#endif

// Scratch (static __device__ per allocation-free rule): 2 x 32MB fp16
__device__ __half g_A[(size_t)M_TOK * K_IN];
__device__ __half g_W[(size_t)N_OUT * K_IN];
__device__ int g_has_tcgen05;   // set by gemm_tc (runs before gemm_hmma)

// ---------------------------------------------------------------------------
// Common PTX helpers
// ---------------------------------------------------------------------------
__device__ __forceinline__ uint32_t smem_to_u32(const void* p) {
    uint32_t a;
    asm("{ .reg .u64 t; cvta.to.shared.u64 t, %1; cvt.u32.u64 %0, t; }"
        : "=r"(a) : "l"(p));
    return a;
}
__device__ __forceinline__ void cp_async16(uint32_t dst, const void* src) {
    asm volatile("cp.async.cg.shared.global [%0], [%1], 16;\n" :: "r"(dst), "l"(src));
}
__device__ __forceinline__ void cp_commit() {
    asm volatile("cp.async.commit_group;\n");
}
template <int N> __device__ __forceinline__ void cp_wait() {
    asm volatile("cp.async.wait_group %0;\n" :: "n"(N));
}
__device__ __forceinline__ void ldsm4(uint32_t* r, uint32_t addr) {
    asm volatile("ldmatrix.sync.aligned.m8n8.x4.shared.b16 {%0,%1,%2,%3}, [%4];"
        : "=r"(r[0]), "=r"(r[1]), "=r"(r[2]), "=r"(r[3]) : "r"(addr));
}
__device__ __forceinline__ void mma16816h(float* c, const uint32_t* a, const uint32_t* b) {
    asm volatile(
        "mma.sync.aligned.m16n8k16.row.col.f32.f16.f16.f32 "
        "{%0,%1,%2,%3}, {%4,%5,%6,%7}, {%8,%9}, {%0,%1,%2,%3};\n"
        : "+f"(c[0]), "+f"(c[1]), "+f"(c[2]), "+f"(c[3])
        : "r"(a[0]), "r"(a[1]), "r"(a[2]), "r"(a[3]), "r"(b[0]), "r"(b[1]));
}

#define MBARRIER_INIT(mbar, count) \
    asm volatile("mbarrier.init.shared.b64 [%0], %1;" \
        :: "r"((uint32_t)(mbar)), "r"((uint32_t)(count)) : "memory")
#define MBARRIER_EXPECT_TX(mbar, tx) \
    asm volatile("mbarrier.arrive.expect_tx.shared.b64 _, [%0], %1;" \
        :: "r"((uint32_t)(mbar)), "r"((uint32_t)(tx)) : "memory")
#define MBARRIER_WAIT_PARITY(mbar, parity) do { \
    uint32_t _m = (uint32_t)(mbar), _p = (uint32_t)(parity), _d; \
    asm volatile("{\n\t.reg .pred p;\n\t" \
        "mbarrier.try_wait.parity.acquire.cta.shared::cta.b64 p, [%1], %2;\n\t" \
        "selp.b32 %0, 1, 0, p;\n\t}" : "=r"(_d) : "r"(_m), "r"(_p) : "memory"); \
    if (!_d) { \
        asm volatile("{\n\t.reg .pred P1;\n\t" \
            "WL_%=:\n\t" \
            "mbarrier.try_wait.parity.acquire.cta.shared::cta.b64 P1, [%0], %1, 0x989680;\n\t" \
            "@P1 bra.uni WD_%=;\n\t" \
            "bra.uni WL_%=;\n\t" \
            "WD_%=:\n\t}" :: "r"(_m), "r"(_p) : "memory"); \
    } \
} while (0)
#define FENCE_PROXY_ASYNC_SHARED_CTA() \
    asm volatile("fence.proxy.async.shared::cta;" ::: "memory")
#define CLUSTER_SYNC() do { \
    asm volatile("barrier.cluster.arrive.aligned;" ::: "memory"); \
    asm volatile("barrier.cluster.wait.aligned;" ::: "memory"); \
} while (0)

// ===========================================================================
// Fused prep: one kernel does x->fp16 (g_A) AND W=sum(alpha*base)->fp16 (g_W).
// X part: 2 x float4 per thread (MLP 2, halved block count).
// W part: 8 elements per thread (MLP 8 on the int32 path).
// `bases` is single-use: streamed with __ldcs.
// ===========================================================================
#define PX_BLOCKS 8192    // (4096*4096/4 float4) / (256 thr * 2 per thr)
#define PX_SPAN   (PX_BLOCKS * 256)       // 2097152 float4 per half
#define PW_BLOCKS 8192    // (4096*4096/8) 8-elem items / 256 threads

__global__ __launch_bounds__(256) void prep_fused(
    const float* __restrict__ x,
    const void* __restrict__ bases_raw,
    const float* __restrict__ alphas) {
    const int tid = threadIdx.x;

    if (blockIdx.x < PX_BLOCKS) {
        // ---- X part: two float4 -> 8 fp16 per thread (one per half of x) ----
        const int i0 = blockIdx.x * 256 + tid;        // first half
        const int i1 = i0 + PX_SPAN;                  // second half
        float4 v0 = ((const float4*)x)[i0];
        float4 v1 = ((const float4*)x)[i1];
        union { __half2 h2[2]; uint2 u; } h0, h1;
        h0.h2[0] = __floats2half2_rn(v0.x, v0.y);
        h0.h2[1] = __floats2half2_rn(v0.z, v0.w);
        h1.h2[0] = __floats2half2_rn(v1.x, v1.y);
        h1.h2[1] = __floats2half2_rn(v1.z, v1.w);
        *(uint2*)(g_A + (size_t)i0 * 4) = h0.u;
        *(uint2*)(g_A + (size_t)i1 * 4) = h1.u;
    } else {
        // ---- W part: 8 elements per thread ----
        const int idx = (blockIdx.x - PX_BLOCKS) * 256 + tid;

        // Per-block dtype detection: if bases is int32, the first 16 words
        // are exactly +/-1; if packed int8, they decode to other patterns.
        const int* bw = (const int*)bases_raw;
        int is_i32 = 1;
        #pragma unroll
        for (int i = 0; i < 16; i++) {
            const int v = __ldg(bw + i);
            if (v != 1 && v != -1) is_i32 = 0;
        }

        const float a0 = __ldg(alphas + 0), a1 = __ldg(alphas + 1);
        const float a2 = __ldg(alphas + 2), a3 = __ldg(alphas + 3);

        float w[8];
        if (is_i32) {
            const size_t plane4 = (size_t)N_OUT * K_IN / 4;  // int4 units
            const int4* b = (const int4*)bases_raw;
            int4 r[4][2];
            #pragma unroll
            for (int k = 0; k < 4; k++) {
                r[k][0] = __ldcs(&b[k * plane4 + (size_t)idx * 2]);
                r[k][1] = __ldcs(&b[k * plane4 + (size_t)idx * 2 + 1]);
            }
            #pragma unroll
            for (int h = 0; h < 2; h++) {
                w[h * 4 + 0] = a0 * (float)r[0][h].x + a1 * (float)r[1][h].x
                             + a2 * (float)r[2][h].x + a3 * (float)r[3][h].x;
                w[h * 4 + 1] = a0 * (float)r[0][h].y + a1 * (float)r[1][h].y
                             + a2 * (float)r[2][h].y + a3 * (float)r[3][h].y;
                w[h * 4 + 2] = a0 * (float)r[0][h].z + a1 * (float)r[1][h].z
                             + a2 * (float)r[2][h].z + a3 * (float)r[3][h].z;
                w[h * 4 + 3] = a0 * (float)r[0][h].w + a1 * (float)r[1][h].w
                             + a2 * (float)r[2][h].w + a3 * (float)r[3][h].w;
            }
        } else {
            const size_t plane8 = (size_t)N_OUT * K_IN / 8;  // 8-byte units
            const uint2* b = (const uint2*)bases_raw;        // 8 int8 per load
            #pragma unroll
            for (int e = 0; e < 8; e++) w[e] = 0.f;
            #pragma unroll
            for (int k = 0; k < 4; k++) {
                const float ak = (k == 0) ? a0 : (k == 1) ? a1 : (k == 2) ? a2 : a3;
                union { uint2 u; char c[8]; } r;
                r.u = __ldcs(&b[k * plane8 + idx]);
                #pragma unroll
                for (int e = 0; e < 8; e++) w[e] += ak * (float)r.c[e];
            }
        }

        union { __half2 h2[4]; uint4 u; } hv;
        hv.h2[0] = __floats2half2_rn(w[0], w[1]);
        hv.h2[1] = __floats2half2_rn(w[2], w[3]);
        hv.h2[2] = __floats2half2_rn(w[4], w[5]);
        hv.h2[3] = __floats2half2_rn(w[6], w[7]);
        *(uint4*)(g_W + (size_t)idx * 8) = hv.u;
    }
}

// ===========================================================================
// Path 1: HMMA (mma.sync) GEMM — fallback if no tcgen05 pass loaded.
// ===========================================================================
#define BKH 32
#define LDT 40
#define TILE_B (128 * LDT * 2)
#define STG_B  (2 * TILE_B)
#define HMMA_SMEM (2 * STG_B)

__global__ __launch_bounds__(256) void gemm_hmma(float* __restrict__ C) {
    if (g_has_tcgen05) return;   // set by gemm_tc, which ran just before

    extern __shared__ char smem[];
    const uint32_t sb = smem_to_u32(smem);
    const int tid = threadIdx.x;
    const int bm = blockIdx.y, bn = blockIdx.x;

    const int lrow = tid >> 2;
    const int lch  = (tid & 3) * 8;
    const __half* gA0 = g_A + (size_t)(bm * 128 + lrow) * K_IN + lch;
    const __half* gB0 = g_W + (size_t)(bn * 128 + lrow) * K_IN + lch;
    const size_t half_rows = (size_t)64 * K_IN;
    const uint32_t dOff = (uint32_t)(lrow * LDT + lch) * 2;
    const uint32_t hOff = 64 * LDT * 2;

    const int warp = tid >> 5, lane = tid & 31;
    const int wm = warp & 1;
    const int wn = warp >> 1;
    const int g  = lane >> 2;
    const int tg = lane & 3;

    const uint32_t aoff =
        ((uint32_t)(wm * 64 + (lane & 7) + ((lane >> 3) & 1) * 8) * LDT
         + ((lane >> 4) & 1) * 8) * 2;
    const uint32_t boff =
        ((uint32_t)(wn * 32 + (lane & 7) + ((lane >> 4) & 1) * 8) * LDT
         + ((lane >> 3) & 1) * 8) * 2;

    float acc[4][4][4];
    #pragma unroll
    for (int mi = 0; mi < 4; mi++)
        #pragma unroll
        for (int ni = 0; ni < 4; ni++)
            #pragma unroll
            for (int e = 0; e < 4; e++) acc[mi][ni][e] = 0.f;

    const int NK = K_IN / BKH;

    {
        uint32_t d = sb + dOff;
        cp_async16(d, gA0);            cp_async16(d + hOff, gA0 + half_rows);
        cp_async16(d + TILE_B, gB0);   cp_async16(d + TILE_B + hOff, gB0 + half_rows);
        cp_commit();
    }

    for (int kt = 0; kt < NK; ++kt) {
        const int buf = kt & 1;
        if (kt + 1 < NK) {
            const int nb = (kt + 1) & 1;
            const size_t ko = (size_t)(kt + 1) * BKH;
            uint32_t d = sb + nb * STG_B + dOff;
            cp_async16(d, gA0 + ko);           cp_async16(d + hOff, gA0 + half_rows + ko);
            cp_async16(d + TILE_B, gB0 + ko);  cp_async16(d + TILE_B + hOff, gB0 + half_rows + ko);
            cp_commit();
            cp_wait<1>();
        } else {
            cp_wait<0>();
        }
        __syncthreads();

        const uint32_t base = sb + buf * STG_B;

        #pragma unroll
        for (int ks2 = 0; ks2 < 2; ks2++) {
            const uint32_t ko = ks2 * 32;
            uint32_t a[4][4], b[2][4];
            #pragma unroll
            for (int mi = 0; mi < 4; mi++)
                ldsm4(a[mi], base + aoff + mi * (16 * LDT * 2) + ko);
            #pragma unroll
            for (int nj = 0; nj < 2; nj++)
                ldsm4(b[nj], base + TILE_B + boff + nj * (16 * LDT * 2) + ko);

            #pragma unroll
            for (int mi = 0; mi < 4; mi++)
                #pragma unroll
                for (int ni = 0; ni < 4; ni++)
                    mma16816h(acc[mi][ni], a[mi], &b[ni >> 1][(ni & 1) * 2]);
        }
        __syncthreads();
    }

    #pragma unroll
    for (int mi = 0; mi < 4; mi++) {
        #pragma unroll
        for (int ni = 0; ni < 4; ni++) {
            const int row = bm * 128 + wm * 64 + mi * 16 + g;
            const int col = bn * 128 + wn * 32 + ni * 8 + tg * 2;
            *(float2*)(C + (size_t)row * N_OUT + col) =
                make_float2(acc[mi][ni][0], acc[mi][ni][1]);
            *(float2*)(C + (size_t)(row + 8) * N_OUT + col) =
                make_float2(acc[mi][ni][2], acc[mi][ni][3]);
        }
    }
}

// ===========================================================================
// Path 2: tcgen05 cg2 fp16 GEMM — proven cluster tile 256x512, BK=64,
// 4 stages, deferred-wait schedule (rounds 11/12/15, 170.0us). Sets
// g_has_tcgen05 (replaces the probe kernel).
// ===========================================================================
#define BM 256            // cluster M
#define BN 512            // cluster N
#define BK 64
#define NCHUNK (K_IN / BK)   // 64
#define STAGES 4
#define A_BYTES (128 * BK * 2)          // 16384 per CTA (its M-half)
#define BSL_BYTES (128 * BK * 2)        // 16384 per B slice
#define STG_BYTES (A_BYTES + 2 * BSL_BYTES)   // 49152 per CTA
#define CL_STG_BYTES (2 * STG_BYTES)          // 98304 per cluster (expect_tx)
#define SM_TMA_FULL(s) ((s) * 8)
#define SM_MMA_DONE(s) (64 + (s) * 8)
#define SM_TMEM_PTR    128
#define SM_TILES       1024
#define SM_A(s)  (SM_TILES + (s) * STG_BYTES)
#define SM_B1(s) (SM_A(s) + A_BYTES)
#define SM_B2(s) (SM_B1(s) + BSL_BYTES)
#define TC_SMEM (SM_TILES + STAGES * STG_BYTES)   // 197632
// idesc kind::f16 cg2: dtype=F32(1<<4), f16 in (atype=btype=0), N=256, M=256
#define GEMM_IDESC ((1u << 4) | ((256u / 8) << 17) | ((256u / 16) << 24))

#if HAS_TC
static constexpr uint64_t SMEM_DESC_BASE_SW128 =
    (uint64_t(2) << 61) | (uint64_t(1) << 46) | (uint64_t(64) << 32) | (uint64_t(1) << 16);
#define MAKE_SMEM_DESC(addr) \
    (SMEM_DESC_BASE_SW128 | ((uint64_t)((addr) >> 4) & 0x3FFF))

__device__ __forceinline__ void mma_f16_ss_cg2(uint32_t d_tmem, uint64_t a_desc,
                                               uint64_t b_desc, uint32_t idesc,
                                               uint32_t enable) {
    asm volatile(
        "{\n\t.reg .pred p;\n\t"
        "setp.ne.u32 p, %5, 0;\n\t"
        "tcgen05.mma.cta_group::2.kind::f16 [%0], %1, %2, %3, "
        "{%4,%4,%4,%4,%4,%4,%4,%4}, p;\n\t}"
        :: "r"(d_tmem), "l"(a_desc), "l"(b_desc), "r"(idesc), "r"(0u), "r"(enable)
        : "memory");
}
// cg2 TMA: both CTAs execute; complete_tx targets the LEADER's barrier
// (clear bit 24 of the local barrier address).
__device__ __forceinline__ void tma_load_2d_cg2(uint32_t smem_addr,
                                                const CUtensorMap* tm,
                                                int x, int y, uint32_t mbar) {
    asm volatile(
        "{\n\t.reg .b32 lb;\n\t"
        "and.b32 lb, %4, 0xFEFFFFFF;\n\t"
        "cp.async.bulk.tensor.2d.cta_group::2.shared::cluster.global.tile"
        ".mbarrier::complete_tx::bytes [%0], [%1, {%2, %3}], [lb];\n\t}"
        :: "r"(smem_addr), "l"(tm), "r"(x), "r"(y), "r"(mbar) : "memory");
}
#define TCGEN05_COMMIT_MC_CG2(mbar, mask) \
    asm volatile("tcgen05.commit.cta_group::2.mbarrier::arrive::one.shared::cluster.multicast::cluster.b64 [%0], %1;" \
        :: "r"((uint32_t)(mbar)), "h"((uint16_t)(mask)) : "memory")
#endif  // HAS_TC

__global__ __launch_bounds__(256, 1) __cluster_dims__(2, 1, 1)
void gemm_tc(
    float* __restrict__ C,
    const __grid_constant__ CUtensorMap tm_a,
    const __grid_constant__ CUtensorMap tm_b) {
#if HAS_TC
    extern __shared__ char smem[];
    const uint32_t sb = smem_to_u32(smem);
    const int tid = threadIdx.x;
    const int wid = tid >> 5, lane = tid & 31;
    const int bm = blockIdx.x >> 1;            // 16 cluster-M tiles
    const int bn = blockIdx.y;                 // 8 cluster-N tiles
    uint32_t rank;
    asm("mov.u32 %0, %%cluster_ctarank;" : "=r"(rank));

    // Replaces the probe kernel: this pass has tcgen05, tell gemm_hmma.
    if (tid == 0 && blockIdx.x == 0 && blockIdx.y == 0) g_has_tcgen05 = 1;

    if (tid == 0) {
        #pragma unroll
        for (int s = 0; s < STAGES; s++) {
            MBARRIER_INIT(sb + SM_TMA_FULL(s), 1);   // leader-only use
            MBARRIER_INIT(sb + SM_MMA_DONE(s), 1);   // one mc-commit arrives
        }
        FENCE_PROXY_ASYNC_SHARED_CTA();
    }
    if (wid == 0) {
        asm volatile("tcgen05.alloc.cta_group::2.sync.aligned.shared::cta.b32 [%0], %1;"
            :: "r"(sb + SM_TMEM_PTR), "r"(512u) : "memory");
        asm volatile("tcgen05.relinquish_alloc_permit.cta_group::2.sync.aligned;");
    }
    __syncthreads();
    CLUSTER_SYNC();   // barriers + TMEM alloc visible before cg2 TMA/MMA

    uint32_t tmem;
    asm volatile("ld.shared.b32 %0, [%1];" : "=r"(tmem) : "r"(sb + SM_TMEM_PTR));
    const uint32_t d1 = tmem;         // N-cols [0,256)  (this CTA's 128 M-rows)
    const uint32_t d2 = tmem + 256;   // N-cols [256,512)

    // Per-CTA TMA coordinates
    const int a_row  = bm * BM + (int)rank * 128;          // A M-half
    const int b1_row = bn * BN + (int)rank * 128;          // B slice, MMA1
    const int b2_row = bn * BN + 256 + (int)rank * 128;    // B slice, MMA2

    if (tid == 0) {
        // Prologue: fill all stages (chunks 0..3)
        #pragma unroll
        for (int p = 0; p < STAGES; p++) {
            if (rank == 0) MBARRIER_EXPECT_TX(sb + SM_TMA_FULL(p), CL_STG_BYTES);
            const int kx = p * BK;
            tma_load_2d_cg2(sb + SM_A(p),  &tm_a, kx, a_row,  sb + SM_TMA_FULL(p));
            tma_load_2d_cg2(sb + SM_B1(p), &tm_b, kx, b1_row, sb + SM_TMA_FULL(p));
            tma_load_2d_cg2(sb + SM_B2(p), &tm_b, kx, b2_row, sb + SM_TMA_FULL(p));
        }

        for (int kt = 0; kt < NCHUNK; kt++) {
            const int s = kt & (STAGES - 1);
            const int ph = (kt / STAGES) & 1;

            if (rank == 0) {
                // Wait both CTAs' stage data (6 loads -> leader barrier).
                MBARRIER_WAIT_PARITY(sb + SM_TMA_FULL(s), ph);
                const uint64_t da  = MAKE_SMEM_DESC(sb + SM_A(s));
                const uint64_t db1 = MAKE_SMEM_DESC(sb + SM_B1(s));
                const uint64_t db2 = MAKE_SMEM_DESC(sb + SM_B2(s));
                #pragma unroll
                for (int ks = 0; ks < 4; ks++) {   // 4 x K16 per BK=64
                    const uint64_t o = (uint64_t)(ks * 2);
                    const uint32_t en = !(kt == 0 && ks == 0);
                    mma_f16_ss_cg2(d1, da + o, db1 + o, GEMM_IDESC, en);
                    mma_f16_ss_cg2(d2, da + o, db2 + o, GEMM_IDESC, en);
                }
                // Arrive on BOTH CTAs' MMA_DONE(s) when this batch completes.
                TCGEN05_COMMIT_MC_CG2(sb + SM_MMA_DONE(s), 3);
            }

            // Deferred refill: stage of chunk kp = kt-1, reloaded with chunk
            // kp+STAGES, gated on chunk kp's MMA completion (local mc-commit
            // arrival). Chunk kt's MMAs are queued behind kp's: tensor pipe
            // stays fed while blocking here.
            const int kp = kt - 1;
            if (kp >= 0 && kp + STAGES < NCHUNK) {
                const int sp = kp & (STAGES - 1);
                const int php = (kp / STAGES) & 1;
                MBARRIER_WAIT_PARITY(sb + SM_MMA_DONE(sp), php);
                if (rank == 0) MBARRIER_EXPECT_TX(sb + SM_TMA_FULL(sp), CL_STG_BYTES);
                const int kx = (kp + STAGES) * BK;
                tma_load_2d_cg2(sb + SM_A(sp),  &tm_a, kx, a_row,  sb + SM_TMA_FULL(sp));
                tma_load_2d_cg2(sb + SM_B1(sp), &tm_b, kx, b1_row, sb + SM_TMA_FULL(sp));
                tma_load_2d_cg2(sb + SM_B2(sp), &tm_b, kx, b2_row, sb + SM_TMA_FULL(sp));
            }
        }
        // Final: wait for the LAST chunk's mc-commit on the local barrier.
        MBARRIER_WAIT_PARITY(sb + SM_MMA_DONE((NCHUNK - 1) & (STAGES - 1)),
                             ((NCHUNK - 1) / STAGES) & 1);
        asm volatile("tcgen05.fence::before_thread_sync;" ::: "memory");
    }
    __syncthreads();

    // Epilogue: each CTA drains its own TMEM (its 128 M-rows x 512 N-cols).
    // Warps 0-3 -> D1 (N-cols 0-255), warps 4-7 -> D2 (N-cols 256-511).
    {
        asm volatile("tcgen05.fence::after_thread_sync;" ::: "memory");
        const uint32_t dbase = (wid < 4) ? d1 : d2;
        const int row = bm * BM + (int)rank * 128 + (wid & 3) * 32 + lane;
        const int col0 = bn * BN + ((wid < 4) ? 0 : 256);
        float* crow = C + (size_t)row * N_OUT + col0;
        #pragma unroll
        for (int base = 0; base < 256; base += 32) {
            uint32_t d[32];
            asm volatile("tcgen05.ld.sync.aligned.32x32b.x32.b32 "
                "{%0,%1,%2,%3,%4,%5,%6,%7,%8,%9,%10,%11,%12,%13,%14,%15,"
                "%16,%17,%18,%19,%20,%21,%22,%23,%24,%25,%26,%27,%28,%29,%30,%31}, [%32];"
                : "=r"(d[0]), "=r"(d[1]), "=r"(d[2]), "=r"(d[3]),
                  "=r"(d[4]), "=r"(d[5]), "=r"(d[6]), "=r"(d[7]),
                  "=r"(d[8]), "=r"(d[9]), "=r"(d[10]), "=r"(d[11]),
                  "=r"(d[12]), "=r"(d[13]), "=r"(d[14]), "=r"(d[15]),
                  "=r"(d[16]), "=r"(d[17]), "=r"(d[18]), "=r"(d[19]),
                  "=r"(d[20]), "=r"(d[21]), "=r"(d[22]), "=r"(d[23]),
                  "=r"(d[24]), "=r"(d[25]), "=r"(d[26]), "=r"(d[27]),
                  "=r"(d[28]), "=r"(d[29]), "=r"(d[30]), "=r"(d[31])
                : "r"(dbase + base));
            asm volatile("tcgen05.wait::ld.sync.aligned;" ::: "memory");
            #pragma unroll
            for (int j = 0; j < 8; j++) {
                float4 v;
                v.x = __uint_as_float(d[4 * j + 0]);
                v.y = __uint_as_float(d[4 * j + 1]);
                v.z = __uint_as_float(d[4 * j + 2]);
                v.w = __uint_as_float(d[4 * j + 3]);
                *(float4*)(crow + base + 4 * j) = v;
            }
        }
    }
    __syncthreads();
    if (wid == 0) {
        asm volatile("tcgen05.dealloc.cta_group::2.sync.aligned.b32 %0, %1;"
            :: "r"(tmem), "r"(512u));
    }
    // Peer MMA may read this CTA's SMEM until the end; TMEM is pair-shared.
    CLUSTER_SYNC();
#endif  // HAS_TC
}

// ---------------------------------------------------------------------------
// Host
// ---------------------------------------------------------------------------
typedef CUresult (*encode_fn_t)(
    CUtensorMap*, CUtensorMapDataType, cuuint32_t, void*,
    const cuuint64_t*, const cuuint64_t*, const cuuint32_t*, const cuuint32_t*,
    CUtensorMapInterleave, CUtensorMapSwizzle, CUtensorMapL2promotion,
    CUtensorMapFloatOOBfill);

static void encode_map(encode_fn_t fn, CUtensorMap* tm, void* base,
                       int rows, uint32_t box_rows) {
    if (!fn) return;
    cuuint64_t dims[2] = {(cuuint64_t)K_IN, (cuuint64_t)rows};
    cuuint64_t strides[1] = {(cuuint64_t)K_IN * 2};
    cuuint32_t box[2] = {(cuuint32_t)BK, box_rows};   // 64 fp16 = 128B = SW128 atom
    cuuint32_t es[2] = {1, 1};
    fn(tm, CU_TENSOR_MAP_DATA_TYPE_FLOAT16, 2, base, dims, strides, box, es,
       CU_TENSOR_MAP_INTERLEAVE_NONE, CU_TENSOR_MAP_SWIZZLE_128B,
       CU_TENSOR_MAP_L2_PROMOTION_L2_128B, CU_TENSOR_MAP_FLOAT_OOB_FILL_NONE);
}

extern "C" void kernel_launch(void* const* d_in, const int* in_sizes, int n_in,
                              void* d_out, int out_size) {
    const float* x = nullptr;
    const float* alphas = nullptr;
    const void* bases = nullptr;
    for (int i = 0; i < n_in; i++) {
        if (in_sizes[i] == 4) alphas = (const float*)d_in[i];
        else if (in_sizes[i] == 16777216) x = (const float*)d_in[i];
        else if (in_sizes[i] == 67108864) bases = (const void*)d_in[i];
    }
    float* y = (float*)d_out;

    void* fnp = nullptr;
    cudaDriverEntryPointQueryResult qst;
#if CUDART_VERSION >= 12050
    cudaGetDriverEntryPointByVersion("cuTensorMapEncodeTiled", &fnp, 12000,
                                     cudaEnableDefault, &qst);
#else
    cudaGetDriverEntryPoint("cuTensorMapEncodeTiled", &fnp, cudaEnableDefault, &qst);
#endif
    encode_fn_t enc = (encode_fn_t)fnp;

    void *pA, *pW;
    cudaGetSymbolAddress(&pA, g_A);
    cudaGetSymbolAddress(&pW, g_W);

    CUtensorMap tm_a = {}, tm_b = {};
    encode_map(enc, &tm_a, pA, M_TOK, 128);    // A box: 64 x 128 (M-half)
    encode_map(enc, &tm_b, pW, N_OUT, 128);    // B box: 64 x 128 (N-slice)

    cudaFuncSetAttribute(gemm_hmma,
                         cudaFuncAttributeMaxDynamicSharedMemorySize, HMMA_SMEM);
    cudaFuncSetAttribute(gemm_tc,
                         cudaFuncAttributeMaxDynamicSharedMemorySize, TC_SMEM);

    // One fused prep launch (x convert + W materialize + inline detection)
    prep_fused<<<PX_BLOCKS + PW_BLOCKS, 256>>>(x, bases, alphas);

    dim3 grid_tc(2 * (M_TOK / BM), N_OUT / BN);   // 32 x 8 CTAs (16x8 clusters)
    gemm_tc<<<grid_tc, 256, TC_SMEM>>>(y, tm_a, tm_b);

    dim3 grid_h(N_OUT / 128, M_TOK / 128);
    gemm_hmma<<<grid_h, 256, HMMA_SMEM>>>(y);
}